// round 12
// baseline (speedup 1.0000x reference)
#include <cuda_runtime.h>
#include <math.h>

#define KCODES 512
#define DDIM   64
#define HDIM   64
#define LN_EPS 1e-5f

#define VT     32      // token-values per dist block
#define CHUNK  32      // codes per dist block
#define NCHUNK 16      // 512 / 32
#define VTILES 16      // 512 / 32
#define NBLK   (VTILES * NCHUNK)   // 256 dist blocks

// device state (zero-initialized at module load; self-reset each replay)
__device__ unsigned long long g_best[KCODES]; // encoded (dist,k) argmin; 0 = empty
__device__ float  g_idx_f[KCODES];            // argmin index per v, as float
__device__ int    g_idx_i[KCODES];            // argmin index per v, as int
__device__ double g_err_lut[KCODES];          // ||cb[idx]-z_v||^2
__device__ int    g_cnt[KCODES];              // histogram of t
__device__ float  g_z[KCODES * DDIM];         // encoder output per v
__device__ int    g_ticket;                   // end-of-kernel ticket

// sortable encoding: max(enc) == (min dist, then min k)
__device__ __forceinline__ unsigned long long enc_best(float d, int k) {
    unsigned int s = __float_as_uint(d);
    s = (s & 0x80000000u) ? ~s : (s | 0x80000000u);   // ascending with d
    return ((unsigned long long)(~s) << 32) |
           (unsigned long long)(0xFFFFFFFFu - (unsigned int)k);
}

// ---------------------------------------------------------------------------
// Kernel 1: fused histogram + encoder + tiled distance/argmin (atomicMax) +
// last-block (err + idx decode + loss + state reset).
// 256 blocks x 256 threads, block = (v-tile of 32) x (code chunk of 32).
// All fp32 accumulations: single accumulator, sequential ascending order —
// identical per-(v,k) dist values to every previous passing round; the
// encoded atomicMax reproduces the strict-< ascending-k tie-break exactly.
// ---------------------------------------------------------------------------
__global__ void dist_kernel(const float* __restrict__ W1,
                            const float* __restrict__ b1,
                            const float* __restrict__ lng,
                            const float* __restrict__ lnb,
                            const float* __restrict__ W2,
                            const float* __restrict__ b2,
                            const float* __restrict__ cb,
                            const int*   __restrict__ t,
                            float*       __restrict__ loss_out,
                            int n) {
    __shared__ float  h_sh[VT * 65];
    __shared__ float  z_sh[VT * 65];
    __shared__ float4 cb_sh4[CHUNK * 16];      // 8 KB, broadcast reads
    __shared__ float  s_mu[VT], s_rs[VT], s_z2[VT], s_e2[CHUNK];
    __shared__ float  s_pd[VT * 8];
    __shared__ int    s_pi[VT * 8];
    __shared__ int    s_glast;
    __shared__ int    sc[KCODES];              // private histogram
    __shared__ double dacc[256];

    const int tid   = threadIdx.x;            // 0..255
    const int vtile = blockIdx.x / NCHUNK;
    const int chunk = blockIdx.x % NCHUNK;
    const int v0    = vtile * VT;
    const int k0    = chunk * CHUNK;

    // ---- private histogram of this block's 1/256 slice of t ----
    sc[tid] = 0;
    sc[tid + 256] = 0;
    __syncthreads();
    {
        const int nq = n >> 2;                 // n divisible by 4
        const int4* t4 = reinterpret_cast<const int4*>(t);
        for (int j = blockIdx.x * 256 + tid; j < nq; j += NBLK * 256) {
            const int4 vv = __ldg(&t4[j]);
            atomicAdd(&sc[vv.x], 1);
            atomicAdd(&sc[vv.y], 1);
            atomicAdd(&sc[vv.z], 1);
            atomicAdd(&sc[vv.w], 1);
        }
    }

    // ---- stage: h = norm*W1 + b1 ; codebook chunk -> smem ----
    for (int idx = tid; idx < VT * HDIM; idx += 256) {
        const int vl = idx >> 6, j = idx & 63;
        const float norm = ((float)(v0 + vl) / (float)(KCODES - 1)) * 2.0f - 1.0f;
        h_sh[vl * 65 + j] = norm * W1[j] + b1[j];
    }
    {
        const float4* src = reinterpret_cast<const float4*>(cb + (size_t)k0 * DDIM);
        for (int j = tid; j < CHUNK * 16; j += 256) cb_sh4[j] = src[j];
    }
    __syncthreads();

    // flush private histogram to global (overlaps with later compute)
    {
        const int c0 = sc[tid], c1 = sc[tid + 256];
        if (c0) atomicAdd(&g_cnt[tid], c0);
        if (c1) atomicAdd(&g_cnt[tid + 256], c1);
    }

    // ---- LN stats (sequential ascending j) ----
    if (tid < VT) {
        float s = 0.0f;
        for (int j = 0; j < HDIM; j++) s += h_sh[tid * 65 + j];
        const float mu = s / (float)HDIM;
        float vs = 0.0f;
        for (int j = 0; j < HDIM; j++) {
            const float d = h_sh[tid * 65 + j] - mu;
            vs += d * d;
        }
        s_mu[tid] = mu;
        s_rs[tid] = 1.0f / sqrtf(vs / (float)HDIM + LN_EPS);
    }
    __syncthreads();

    // ---- LN + relu ----
    for (int idx = tid; idx < VT * HDIM; idx += 256) {
        const int vl = idx >> 6, j = idx & 63;
        float x = (h_sh[vl * 65 + j] - s_mu[vl]) * s_rs[vl] * lng[j] + lnb[j];
        h_sh[vl * 65 + j] = fmaxf(x, 0.0f);
    }
    __syncthreads();

    // ---- z = h @ W2 + b2 (sequential ascending j) ----
    for (int idx = tid; idx < VT * DDIM; idx += 256) {
        const int vl = idx >> 6, d = idx & 63;
        float acc = 0.0f;
        for (int j = 0; j < HDIM; j++)
            acc += h_sh[vl * 65 + j] * __ldg(&W2[j * DDIM + d]);
        z_sh[vl * 65 + d] = acc + b2[d];
    }
    __syncthreads();

    // ---- z2 (warp 0), e2 per code (warp 1), persist z (chunk 0 blocks) ----
    if (tid < VT) {
        float s = 0.0f;
        for (int d = 0; d < DDIM; d++) {
            const float zz = z_sh[tid * 65 + d];
            s += zz * zz;
        }
        s_z2[tid] = s;
    } else if (tid < VT + CHUNK) {
        const int kl = tid - VT;
        const float4* e = reinterpret_cast<const float4*>(cb + (size_t)(k0 + kl) * DDIM);
        float acc = 0.0f;
        #pragma unroll
        for (int i = 0; i < DDIM / 4; i++) {
            const float4 c = e[i];
            acc += c.x * c.x;
            acc += c.y * c.y;
            acc += c.z * c.z;
            acc += c.w * c.w;
        }
        s_e2[kl] = acc;
    }
    if (chunk == 0) {
        for (int idx = tid; idx < VT * DDIM; idx += 256) {
            const int vl = idx >> 6, d = idx & 63;
            g_z[(v0 + vl) * DDIM + d] = z_sh[vl * 65 + d];
        }
    }
    __syncthreads();

    // ---- dot products: thread (vl, kg) handles 4 contiguous codes ----
    const int vl = tid & 31;
    const int kg = tid >> 5;

    float dot0 = 0.0f, dot1 = 0.0f, dot2 = 0.0f, dot3 = 0.0f;
    #pragma unroll
    for (int ch = 0; ch < 4; ch++) {                   // d-chunks of 16
        float zz[16];
        #pragma unroll
        for (int q = 0; q < 16; q++) zz[q] = z_sh[vl * 65 + ch * 16 + q];
        #pragma unroll
        for (int c = 0; c < 4; c++) {
            const float4* e = &cb_sh4[(kg * 4 + c) * 16 + ch * 4];
            float* dp = (c == 0) ? &dot0 : (c == 1) ? &dot1 : (c == 2) ? &dot2 : &dot3;
            #pragma unroll
            for (int i = 0; i < 4; i++) {
                const float4 cc = e[i];
                *dp += zz[i * 4 + 0] * cc.x;
                *dp += zz[i * 4 + 1] * cc.y;
                *dp += zz[i * 4 + 2] * cc.z;
                *dp += zz[i * 4 + 3] * cc.w;
            }
        }
    }
    const float z2 = s_z2[vl];
    float bestD = INFINITY;
    int   bestI = 0;
    {
        float dists[4] = {z2 - 2.0f * dot0 + s_e2[kg * 4 + 0],
                          z2 - 2.0f * dot1 + s_e2[kg * 4 + 1],
                          z2 - 2.0f * dot2 + s_e2[kg * 4 + 2],
                          z2 - 2.0f * dot3 + s_e2[kg * 4 + 3]};
        #pragma unroll
        for (int c = 0; c < 4; c++) {
            if (dists[c] < bestD) { bestD = dists[c]; bestI = k0 + kg * 4 + c; }
        }
    }
    s_pd[vl * 8 + kg] = bestD;
    s_pi[vl * 8 + kg] = bestI;
    __syncthreads();

    // combine across kg ascending (strict <), then one atomicMax per v
    if (tid < VT) {
        float bd = INFINITY;
        int   bi = 0;
        for (int g = 0; g < 8; g++) {
            const float d2 = s_pd[tid * 8 + g];
            if (d2 < bd) { bd = d2; bi = s_pi[tid * 8 + g]; }
        }
        atomicMax(&g_best[v0 + tid], enc_best(bd, bi));
    }

    // ---- single global ticket: last block finalizes everything ----
    __threadfence();
    if (tid == 0) {
        const int gt = atomicAdd(&g_ticket, 1);
        s_glast = (gt == NBLK - 1) ? 1 : 0;
    }
    __syncthreads();
    if (!s_glast) return;
    __threadfence();

    // decode argmin, compute per-v double error (thread handles v and v+256)
    #pragma unroll
    for (int half = 0; half < 2; half++) {
        const int v = tid + half * 256;
        const unsigned long long e = g_best[v];
        const int bi = (int)(0xFFFFFFFFu - (unsigned int)(e & 0xFFFFFFFFull));
        g_idx_i[v] = bi;
        g_idx_f[v] = (float)bi;
        g_best[v]  = 0ull;                     // reset for next replay

        const float* cbp = cb + (size_t)bi * DDIM;
        const float* zp  = g_z + v * DDIM;
        double a0 = 0.0, a1 = 0.0, a2 = 0.0, a3 = 0.0;
        for (int d = 0; d < DDIM; d += 4) {
            const double f0 = (double)cbp[d + 0] - (double)zp[d + 0];
            const double f1 = (double)cbp[d + 1] - (double)zp[d + 1];
            const double f2 = (double)cbp[d + 2] - (double)zp[d + 2];
            const double f3 = (double)cbp[d + 3] - (double)zp[d + 3];
            a0 += f0 * f0; a1 += f1 * f1; a2 += f2 * f2; a3 += f3 * f3;
        }
        g_err_lut[v] = (a0 + a1) + (a2 + a3);
    }
    __syncthreads();

    // loss from completed histogram + errors, then reset hist/ticket
    dacc[tid] = (double)g_cnt[tid]       * g_err_lut[tid]
              + (double)g_cnt[tid + 256] * g_err_lut[tid + 256];
    g_cnt[tid] = 0;
    g_cnt[tid + 256] = 0;
    if (tid == 0) g_ticket = 0;
    __syncthreads();
    for (int off = 128; off > 0; off >>= 1) {
        if (tid < off) dacc[tid] += dacc[tid + off];
        __syncthreads();
    }
    if (tid == 0 && loss_out != nullptr) {
        loss_out[0] = (float)(1.25 * dacc[0] / ((double)n * (double)DDIM));
    }
}

// ---------------------------------------------------------------------------
// Kernel 2: scatter — proven memory pattern; gathers codebook rows directly
// via g_idx_i (no q-LUT). No smem, no atomics, no fences.
// ---------------------------------------------------------------------------
#define SC_UNROLL 4
__global__ void scatter_kernel(const int* __restrict__ t,
                               const float4* __restrict__ cb4,
                               float4* __restrict__ q_out,
                               float* __restrict__ idx_out, int n) {
    const int total  = n * 16;
    const int stride = gridDim.x * blockDim.x;
    const int i0     = blockIdx.x * blockDim.x + threadIdx.x;

    int    v[SC_UNROLL];
    int    ix[SC_UNROLL];
    float4 val[SC_UNROLL];

    #pragma unroll
    for (int j = 0; j < SC_UNROLL; j++) {
        const int i = i0 + j * stride;
        if (i < total) {
            v[j]   = __ldg(t + (i >> 4));
            ix[j]  = __ldg(&g_idx_i[v[j]]);
            val[j] = __ldg(&cb4[(ix[j] << 4) + (i & 15)]);
        } else {
            v[j] = -1;
        }
    }

    #pragma unroll
    for (int j = 0; j < SC_UNROLL; j++) {
        const int i = i0 + j * stride;
        if (v[j] >= 0) {
            q_out[i] = val[j];
            if ((i & 15) == 0 && idx_out != nullptr) {
                idx_out[i >> 4] = g_idx_f[v[j]];
            }
        }
    }
}

// ---------------------------------------------------------------------------
extern "C" void kernel_launch(void* const* d_in, const int* in_sizes, int n_in,
                              void* d_out, int out_size) {
    const int*   t    = (const int*)d_in[0];
    const float* W1   = (const float*)d_in[1];
    const float* b1   = (const float*)d_in[2];
    const float* lng  = (const float*)d_in[3];
    const float* lnb  = (const float*)d_in[4];
    const float* W2   = (const float*)d_in[5];
    const float* b2   = (const float*)d_in[6];
    const float* cb   = (const float*)d_in[7];

    const int n = in_sizes[0];                 // N = B*T = 262144 tokens
    float* out = (float*)d_out;

    // Output layout: [ q : n*64 floats | idx : n floats | loss : 1 float ]
    const bool full = (out_size >= n * DDIM + n + 1);
    float* q_out    = out;
    float* idx_out  = full ? (out + (size_t)n * DDIM) : nullptr;
    float* loss_out = full ? (out + (size_t)n * DDIM + n) : nullptr;

    dist_kernel<<<NBLK, 256>>>(W1, b1, lng, lnb, W2, b2, cb, t, loss_out, n);

    const int total   = n * 16;
    const int threads = 256;
    const int blocks  = (total + threads * SC_UNROLL - 1) / (threads * SC_UNROLL);
    scatter_kernel<<<blocks, threads>>>(t, (const float4*)cb,
                                        (float4*)q_out, idx_out, n);
}

// round 13
// speedup vs baseline: 1.6657x; 1.6657x over previous
#include <cuda_runtime.h>
#include <math.h>

#define KCODES 512
#define DDIM   64
#define HDIM   64
#define LN_EPS 1e-5f

#define VT     32      // token-values per dist block
#define CHUNK  32      // codes per dist block
#define NCHUNK 16      // 512 / 32
#define VTILES 16      // 512 / 32
#define NBLK   (VTILES * NCHUNK)   // 256 dist blocks

// device scratch / LUTs (zero-initialized at module load)
__device__ float4 g_q_lut4[KCODES * 16];      // chosen codebook row per v (float4 view)
__device__ float  g_idx_f[KCODES];            // argmin index per v, as float
__device__ double g_err_lut[KCODES];          // ||cb[idx]-z_v||^2
__device__ int    g_cnt[KCODES];              // histogram of t (reset by scatter)
__device__ float  g_z[KCODES * DDIM];         // encoder output per v
__device__ float  g_pd[KCODES * NCHUNK];      // partial best dist per (v,chunk)
__device__ int    g_pi[KCODES * NCHUNK];      // partial best idx  per (v,chunk)
__device__ int    g_tile_cnt[VTILES];         // per-vtile tickets
__device__ int    g_ticket;                   // ticket among vtile-last blocks

// ---------------------------------------------------------------------------
// Kernel 1: fused histogram + encoder + tiled distance/argmin + LUT fill +
// loss. 256 blocks x 256 threads. Block = (v-tile of 32) x (code chunk of 32).
// Structure identical to the round-6 champion (45.57us total); the only
// change is W2 staged through shared memory (bit-identical values, same
// sequential ascending accumulation order).
// ---------------------------------------------------------------------------
__global__ void dist_kernel(const float* __restrict__ W1,
                            const float* __restrict__ b1,
                            const float* __restrict__ lng,
                            const float* __restrict__ lnb,
                            const float* __restrict__ W2,
                            const float* __restrict__ b2,
                            const float* __restrict__ cb,
                            const int*   __restrict__ t,
                            float*       __restrict__ loss_out,
                            int n) {
    __shared__ float  h_sh[VT * 65];
    __shared__ float  z_sh[VT * 65];
    __shared__ float  w2_sh[HDIM * DDIM];      // 16 KB staged W2
    __shared__ float4 cb_sh4[CHUNK * 16];      // 8 KB, broadcast reads
    __shared__ float  s_mu[VT], s_rs[VT], s_z2[VT], s_e2[CHUNK];
    __shared__ float  s_pd[VT * 8];
    __shared__ int    s_pi[VT * 8];
    __shared__ int    s_last, s_glast;
    __shared__ int    s_bestv[VT];
    __shared__ int    sc[KCODES];              // private histogram
    __shared__ double dacc[256];

    const int tid   = threadIdx.x;            // 0..255
    const int vtile = blockIdx.x / NCHUNK;
    const int chunk = blockIdx.x % NCHUNK;
    const int v0    = vtile * VT;
    const int k0    = chunk * CHUNK;

    // ---- private histogram of this block's 1/256 slice of t ----
    sc[tid] = 0;
    sc[tid + 256] = 0;
    __syncthreads();
    {
        const int nq = n >> 2;                 // n divisible by 4
        const int4* t4 = reinterpret_cast<const int4*>(t);
        for (int j = blockIdx.x * 256 + tid; j < nq; j += NBLK * 256) {
            const int4 vv = __ldg(&t4[j]);
            atomicAdd(&sc[vv.x], 1);
            atomicAdd(&sc[vv.y], 1);
            atomicAdd(&sc[vv.z], 1);
            atomicAdd(&sc[vv.w], 1);
        }
    }

    // ---- stage: h = norm*W1 + b1 ; W2 -> smem ; codebook chunk -> smem ----
    for (int idx = tid; idx < VT * HDIM; idx += 256) {
        const int vl = idx >> 6, j = idx & 63;
        const float norm = ((float)(v0 + vl) / (float)(KCODES - 1)) * 2.0f - 1.0f;
        h_sh[vl * 65 + j] = norm * W1[j] + b1[j];
    }
    {
        const float4* w2s = reinterpret_cast<const float4*>(W2);
        float4* w2d = reinterpret_cast<float4*>(w2_sh);
        for (int j = tid; j < HDIM * DDIM / 4; j += 256) w2d[j] = w2s[j];
        const float4* src = reinterpret_cast<const float4*>(cb + (size_t)k0 * DDIM);
        for (int j = tid; j < CHUNK * 16; j += 256) cb_sh4[j] = src[j];
    }
    __syncthreads();

    // flush private histogram to global (overlaps with later compute)
    {
        const int c0 = sc[tid], c1 = sc[tid + 256];
        if (c0) atomicAdd(&g_cnt[tid], c0);
        if (c1) atomicAdd(&g_cnt[tid + 256], c1);
    }

    // ---- LN stats (sequential ascending j) ----
    if (tid < VT) {
        float s = 0.0f;
        for (int j = 0; j < HDIM; j++) s += h_sh[tid * 65 + j];
        const float mu = s / (float)HDIM;
        float vs = 0.0f;
        for (int j = 0; j < HDIM; j++) {
            const float d = h_sh[tid * 65 + j] - mu;
            vs += d * d;
        }
        s_mu[tid] = mu;
        s_rs[tid] = 1.0f / sqrtf(vs / (float)HDIM + LN_EPS);
    }
    __syncthreads();

    // ---- LN + relu ----
    for (int idx = tid; idx < VT * HDIM; idx += 256) {
        const int vl = idx >> 6, j = idx & 63;
        float x = (h_sh[vl * 65 + j] - s_mu[vl]) * s_rs[vl] * lng[j] + lnb[j];
        h_sh[vl * 65 + j] = fmaxf(x, 0.0f);
    }
    __syncthreads();

    // ---- z = h @ W2 + b2 (sequential ascending j, single accumulator) ----
    for (int idx = tid; idx < VT * DDIM; idx += 256) {
        const int vl = idx >> 6, d = idx & 63;
        float acc = 0.0f;
        for (int j = 0; j < HDIM; j++)
            acc += h_sh[vl * 65 + j] * w2_sh[j * DDIM + d];
        z_sh[vl * 65 + d] = acc + b2[d];
    }
    __syncthreads();

    // ---- z2 (warp 0), e2 per code (warp 1), persist z (chunk 0 blocks) ----
    if (tid < VT) {
        float s = 0.0f;
        for (int d = 0; d < DDIM; d++) {
            const float zz = z_sh[tid * 65 + d];
            s += zz * zz;
        }
        s_z2[tid] = s;
    } else if (tid < VT + CHUNK) {
        const int kl = tid - VT;
        const float4* e = reinterpret_cast<const float4*>(cb + (size_t)(k0 + kl) * DDIM);
        float acc = 0.0f;
        #pragma unroll
        for (int i = 0; i < DDIM / 4; i++) {
            const float4 c = e[i];
            acc += c.x * c.x;
            acc += c.y * c.y;
            acc += c.z * c.z;
            acc += c.w * c.w;
        }
        s_e2[kl] = acc;
    }
    if (chunk == 0) {
        for (int idx = tid; idx < VT * DDIM; idx += 256) {
            const int vl = idx >> 6, d = idx & 63;
            g_z[(v0 + vl) * DDIM + d] = z_sh[vl * 65 + d];
        }
    }
    __syncthreads();

    // ---- dot products: thread (vl, kg) handles 4 contiguous codes ----
    const int vl = tid & 31;
    const int kg = tid >> 5;

    float dot0 = 0.0f, dot1 = 0.0f, dot2 = 0.0f, dot3 = 0.0f;
    #pragma unroll
    for (int ch = 0; ch < 4; ch++) {                   // d-chunks of 16
        float zz[16];
        #pragma unroll
        for (int q = 0; q < 16; q++) zz[q] = z_sh[vl * 65 + ch * 16 + q];
        #pragma unroll
        for (int c = 0; c < 4; c++) {
            const float4* e = &cb_sh4[(kg * 4 + c) * 16 + ch * 4];
            float* dp = (c == 0) ? &dot0 : (c == 1) ? &dot1 : (c == 2) ? &dot2 : &dot3;
            #pragma unroll
            for (int i = 0; i < 4; i++) {
                const float4 cc = e[i];
                *dp += zz[i * 4 + 0] * cc.x;
                *dp += zz[i * 4 + 1] * cc.y;
                *dp += zz[i * 4 + 2] * cc.z;
                *dp += zz[i * 4 + 3] * cc.w;
            }
        }
    }
    const float z2 = s_z2[vl];
    float bestD = INFINITY;
    int   bestI = 0;
    {
        float dists[4] = {z2 - 2.0f * dot0 + s_e2[kg * 4 + 0],
                          z2 - 2.0f * dot1 + s_e2[kg * 4 + 1],
                          z2 - 2.0f * dot2 + s_e2[kg * 4 + 2],
                          z2 - 2.0f * dot3 + s_e2[kg * 4 + 3]};
        #pragma unroll
        for (int c = 0; c < 4; c++) {
            if (dists[c] < bestD) { bestD = dists[c]; bestI = k0 + kg * 4 + c; }
        }
    }
    s_pd[vl * 8 + kg] = bestD;
    s_pi[vl * 8 + kg] = bestI;
    __syncthreads();

    // combine across kg ascending, publish chunk partials
    if (tid < VT) {
        float bd = INFINITY;
        int   bi = 0;
        for (int g = 0; g < 8; g++) {
            const float d2 = s_pd[tid * 8 + g];
            if (d2 < bd) { bd = d2; bi = s_pi[tid * 8 + g]; }
        }
        g_pd[(v0 + tid) * NCHUNK + chunk] = bd;
        g_pi[(v0 + tid) * NCHUNK + chunk] = bi;
    }

    // ---- per-vtile last block: combine chunks, fill LUTs ----
    __threadfence();
    if (tid == 0) {
        const int ticket = atomicAdd(&g_tile_cnt[vtile], 1);
        s_last = (ticket == NCHUNK - 1) ? 1 : 0;
    }
    __syncthreads();

    if (s_last) {
        __threadfence();
        if (tid < VT) {
            const int v = v0 + tid;
            float bd = INFINITY;
            int   bi = 0;
            for (int c = 0; c < NCHUNK; c++) {       // ascending chunk = ascending k
                const float d = g_pd[v * NCHUNK + c];
                if (d < bd) { bd = d; bi = g_pi[v * NCHUNK + c]; }
            }
            s_bestv[tid] = bi;
            g_idx_f[v]   = (float)bi;

            const float* e  = cb + (size_t)bi * DDIM;
            const float* zp = g_z + v * DDIM;
            double a0 = 0.0, a1 = 0.0, a2 = 0.0, a3 = 0.0;
            for (int d = 0; d < DDIM; d += 4) {
                const double f0 = (double)e[d + 0] - (double)zp[d + 0];
                const double f1 = (double)e[d + 1] - (double)zp[d + 1];
                const double f2 = (double)e[d + 2] - (double)zp[d + 2];
                const double f3 = (double)e[d + 3] - (double)zp[d + 3];
                a0 += f0 * f0; a1 += f1 * f1; a2 += f2 * f2; a3 += f3 * f3;
            }
            g_err_lut[v] = (a0 + a1) + (a2 + a3);
        }
        __syncthreads();

        float* q_lut = reinterpret_cast<float*>(g_q_lut4);
        for (int idx = tid; idx < VT * DDIM; idx += 256) {
            const int vvl = idx >> 6, d = idx & 63;
            q_lut[(v0 + vvl) * DDIM + d] = cb[(size_t)s_bestv[vvl] * DDIM + d];
        }
        if (tid == 0) g_tile_cnt[vtile] = 0;         // clean for next replay

        // ---- ticket-of-tickets: last vtile-last block computes the loss ----
        __threadfence();
        if (tid == 0) {
            const int gt = atomicAdd(&g_ticket, 1);
            s_glast = (gt == VTILES - 1) ? 1 : 0;
        }
        __syncthreads();
        if (s_glast) {
            __threadfence();
            if (tid == 0) g_ticket = 0;              // clean for next replay
            if (loss_out != nullptr) {
                dacc[tid] = (double)g_cnt[tid]       * g_err_lut[tid]
                          + (double)g_cnt[tid + 256] * g_err_lut[tid + 256];
                __syncthreads();
                for (int off = 128; off > 0; off >>= 1) {
                    if (tid < off) dacc[tid] += dacc[tid + off];
                    __syncthreads();
                }
                if (tid == 0)
                    loss_out[0] = (float)(1.25 * dacc[0] /
                                          ((double)n * (double)DDIM));
            }
        }
    }
}

// ---------------------------------------------------------------------------
// Kernel 2: scatter — R12 shape (measured 16.9us), single hop through the
// q-LUT. No smem, no atomics, no fences. Block 0 resets g_cnt for replay.
// ---------------------------------------------------------------------------
#define SC_UNROLL 4
__global__ void scatter_kernel(const int* __restrict__ t,
                               float4* __restrict__ q_out,
                               float* __restrict__ idx_out, int n) {
    if (blockIdx.x == 0) {                      // reset hist for next replay
        g_cnt[threadIdx.x] = 0;
        g_cnt[threadIdx.x + 256] = 0;
    }
    const int total  = n * 16;
    const int stride = gridDim.x * blockDim.x;
    const int i0     = blockIdx.x * blockDim.x + threadIdx.x;

    int    v[SC_UNROLL];
    float4 val[SC_UNROLL];

    #pragma unroll
    for (int j = 0; j < SC_UNROLL; j++) {
        const int i = i0 + j * stride;
        if (i < total) {
            v[j]   = __ldg(t + (i >> 4));
            val[j] = __ldg(&g_q_lut4[(v[j] << 4) + (i & 15)]);
        } else {
            v[j] = -1;
        }
    }

    #pragma unroll
    for (int j = 0; j < SC_UNROLL; j++) {
        const int i = i0 + j * stride;
        if (v[j] >= 0) {
            q_out[i] = val[j];
            if ((i & 15) == 0 && idx_out != nullptr) {
                idx_out[i >> 4] = g_idx_f[v[j]];
            }
        }
    }
}

// ---------------------------------------------------------------------------
extern "C" void kernel_launch(void* const* d_in, const int* in_sizes, int n_in,
                              void* d_out, int out_size) {
    const int*   t    = (const int*)d_in[0];
    const float* W1   = (const float*)d_in[1];
    const float* b1   = (const float*)d_in[2];
    const float* lng  = (const float*)d_in[3];
    const float* lnb  = (const float*)d_in[4];
    const float* W2   = (const float*)d_in[5];
    const float* b2   = (const float*)d_in[6];
    const float* cb   = (const float*)d_in[7];

    const int n = in_sizes[0];                 // N = B*T = 262144 tokens
    float* out = (float*)d_out;

    // Output layout: [ q : n*64 floats | idx : n floats | loss : 1 float ]
    const bool full = (out_size >= n * DDIM + n + 1);
    float* q_out    = out;
    float* idx_out  = full ? (out + (size_t)n * DDIM) : nullptr;
    float* loss_out = full ? (out + (size_t)n * DDIM + n) : nullptr;

    dist_kernel<<<NBLK, 256>>>(W1, b1, lng, lnb, W2, b2, cb, t, loss_out, n);

    const int total   = n * 16;
    const int threads = 256;
    const int blocks  = (total + threads * SC_UNROLL - 1) / (threads * SC_UNROLL);
    scatter_kernel<<<blocks, threads>>>(t, (float4*)q_out, idx_out, n);
}

// round 14
// speedup vs baseline: 1.6728x; 1.0042x over previous
#include <cuda_runtime.h>
#include <math.h>

#define KCODES 512
#define DDIM   64
#define HDIM   64
#define LN_EPS 1e-5f

#define VT     32      // token-values per dist block
#define CHUNK  32      // codes per dist block
#define NCHUNK 16      // 512 / 32
#define VTILES 16      // 512 / 32
#define NBLK   (VTILES * NCHUNK)   // 256 dist blocks

#define SC_GRID 148
#define SC_TPB  1024
#define SC_SMEM (KCODES * DDIM * 4 + KCODES * 4)   // 128 KB LUT + 2 KB idx

// device scratch / LUTs (zero-initialized at module load)
__device__ float4 g_q_lut4[KCODES * 16];      // chosen codebook row per v (float4 view)
__device__ float  g_idx_f[KCODES];            // argmin index per v, as float
__device__ double g_err_lut[KCODES];          // ||cb[idx]-z_v||^2
__device__ int    g_cnt[KCODES];              // histogram of t (reset by scatter)
__device__ float  g_z[KCODES * DDIM];         // encoder output per v
__device__ float  g_pd[KCODES * NCHUNK];      // partial best dist per (v,chunk)
__device__ int    g_pi[KCODES * NCHUNK];      // partial best idx  per (v,chunk)
__device__ int    g_tile_cnt[VTILES];         // per-vtile tickets
__device__ int    g_ticket;                   // ticket among vtile-last blocks

// ---------------------------------------------------------------------------
// Kernel 1: fused histogram + encoder + tiled distance/argmin + LUT fill +
// loss. 256 blocks x 256 threads — identical to the round-13/champion kernel.
// All fp32 accumulations: single accumulator, sequential ascending order,
// strict-< ascending-k argmin (rel_err stable at 1.423831e-05 since round 1).
// ---------------------------------------------------------------------------
__global__ void dist_kernel(const float* __restrict__ W1,
                            const float* __restrict__ b1,
                            const float* __restrict__ lng,
                            const float* __restrict__ lnb,
                            const float* __restrict__ W2,
                            const float* __restrict__ b2,
                            const float* __restrict__ cb,
                            const int*   __restrict__ t,
                            float*       __restrict__ loss_out,
                            int n) {
    __shared__ float  h_sh[VT * 65];
    __shared__ float  z_sh[VT * 65];
    __shared__ float  w2_sh[HDIM * DDIM];      // 16 KB staged W2
    __shared__ float4 cb_sh4[CHUNK * 16];      // 8 KB, broadcast reads
    __shared__ float  s_mu[VT], s_rs[VT], s_z2[VT], s_e2[CHUNK];
    __shared__ float  s_pd[VT * 8];
    __shared__ int    s_pi[VT * 8];
    __shared__ int    s_last, s_glast;
    __shared__ int    s_bestv[VT];
    __shared__ int    sc[KCODES];              // private histogram
    __shared__ double dacc[256];

    const int tid   = threadIdx.x;            // 0..255
    const int vtile = blockIdx.x / NCHUNK;
    const int chunk = blockIdx.x % NCHUNK;
    const int v0    = vtile * VT;
    const int k0    = chunk * CHUNK;

    // ---- private histogram of this block's 1/256 slice of t ----
    sc[tid] = 0;
    sc[tid + 256] = 0;
    __syncthreads();
    {
        const int nq = n >> 2;                 // n divisible by 4
        const int4* t4 = reinterpret_cast<const int4*>(t);
        for (int j = blockIdx.x * 256 + tid; j < nq; j += NBLK * 256) {
            const int4 vv = __ldg(&t4[j]);
            atomicAdd(&sc[vv.x], 1);
            atomicAdd(&sc[vv.y], 1);
            atomicAdd(&sc[vv.z], 1);
            atomicAdd(&sc[vv.w], 1);
        }
    }

    // ---- stage: h = norm*W1 + b1 ; W2 -> smem ; codebook chunk -> smem ----
    for (int idx = tid; idx < VT * HDIM; idx += 256) {
        const int vl = idx >> 6, j = idx & 63;
        const float norm = ((float)(v0 + vl) / (float)(KCODES - 1)) * 2.0f - 1.0f;
        h_sh[vl * 65 + j] = norm * W1[j] + b1[j];
    }
    {
        const float4* w2s = reinterpret_cast<const float4*>(W2);
        float4* w2d = reinterpret_cast<float4*>(w2_sh);
        for (int j = tid; j < HDIM * DDIM / 4; j += 256) w2d[j] = w2s[j];
        const float4* src = reinterpret_cast<const float4*>(cb + (size_t)k0 * DDIM);
        for (int j = tid; j < CHUNK * 16; j += 256) cb_sh4[j] = src[j];
    }
    __syncthreads();

    // flush private histogram to global (overlaps with later compute)
    {
        const int c0 = sc[tid], c1 = sc[tid + 256];
        if (c0) atomicAdd(&g_cnt[tid], c0);
        if (c1) atomicAdd(&g_cnt[tid + 256], c1);
    }

    // ---- LN stats (sequential ascending j) ----
    if (tid < VT) {
        float s = 0.0f;
        for (int j = 0; j < HDIM; j++) s += h_sh[tid * 65 + j];
        const float mu = s / (float)HDIM;
        float vs = 0.0f;
        for (int j = 0; j < HDIM; j++) {
            const float d = h_sh[tid * 65 + j] - mu;
            vs += d * d;
        }
        s_mu[tid] = mu;
        s_rs[tid] = 1.0f / sqrtf(vs / (float)HDIM + LN_EPS);
    }
    __syncthreads();

    // ---- LN + relu ----
    for (int idx = tid; idx < VT * HDIM; idx += 256) {
        const int vl = idx >> 6, j = idx & 63;
        float x = (h_sh[vl * 65 + j] - s_mu[vl]) * s_rs[vl] * lng[j] + lnb[j];
        h_sh[vl * 65 + j] = fmaxf(x, 0.0f);
    }
    __syncthreads();

    // ---- z = h @ W2 + b2 (sequential ascending j, single accumulator) ----
    for (int idx = tid; idx < VT * DDIM; idx += 256) {
        const int vl = idx >> 6, d = idx & 63;
        float acc = 0.0f;
        for (int j = 0; j < HDIM; j++)
            acc += h_sh[vl * 65 + j] * w2_sh[j * DDIM + d];
        z_sh[vl * 65 + d] = acc + b2[d];
    }
    __syncthreads();

    // ---- z2 (warp 0), e2 per code (warp 1), persist z (chunk 0 blocks) ----
    if (tid < VT) {
        float s = 0.0f;
        for (int d = 0; d < DDIM; d++) {
            const float zz = z_sh[tid * 65 + d];
            s += zz * zz;
        }
        s_z2[tid] = s;
    } else if (tid < VT + CHUNK) {
        const int kl = tid - VT;
        const float4* e = reinterpret_cast<const float4*>(cb + (size_t)(k0 + kl) * DDIM);
        float acc = 0.0f;
        #pragma unroll
        for (int i = 0; i < DDIM / 4; i++) {
            const float4 c = e[i];
            acc += c.x * c.x;
            acc += c.y * c.y;
            acc += c.z * c.z;
            acc += c.w * c.w;
        }
        s_e2[kl] = acc;
    }
    if (chunk == 0) {
        for (int idx = tid; idx < VT * DDIM; idx += 256) {
            const int vl = idx >> 6, d = idx & 63;
            g_z[(v0 + vl) * DDIM + d] = z_sh[vl * 65 + d];
        }
    }
    __syncthreads();

    // ---- dot products: thread (vl, kg) handles 4 contiguous codes ----
    const int vl = tid & 31;
    const int kg = tid >> 5;

    float dot0 = 0.0f, dot1 = 0.0f, dot2 = 0.0f, dot3 = 0.0f;
    #pragma unroll
    for (int ch = 0; ch < 4; ch++) {                   // d-chunks of 16
        float zz[16];
        #pragma unroll
        for (int q = 0; q < 16; q++) zz[q] = z_sh[vl * 65 + ch * 16 + q];
        #pragma unroll
        for (int c = 0; c < 4; c++) {
            const float4* e = &cb_sh4[(kg * 4 + c) * 16 + ch * 4];
            float* dp = (c == 0) ? &dot0 : (c == 1) ? &dot1 : (c == 2) ? &dot2 : &dot3;
            #pragma unroll
            for (int i = 0; i < 4; i++) {
                const float4 cc = e[i];
                *dp += zz[i * 4 + 0] * cc.x;
                *dp += zz[i * 4 + 1] * cc.y;
                *dp += zz[i * 4 + 2] * cc.z;
                *dp += zz[i * 4 + 3] * cc.w;
            }
        }
    }
    const float z2 = s_z2[vl];
    float bestD = INFINITY;
    int   bestI = 0;
    {
        float dists[4] = {z2 - 2.0f * dot0 + s_e2[kg * 4 + 0],
                          z2 - 2.0f * dot1 + s_e2[kg * 4 + 1],
                          z2 - 2.0f * dot2 + s_e2[kg * 4 + 2],
                          z2 - 2.0f * dot3 + s_e2[kg * 4 + 3]};
        #pragma unroll
        for (int c = 0; c < 4; c++) {
            if (dists[c] < bestD) { bestD = dists[c]; bestI = k0 + kg * 4 + c; }
        }
    }
    s_pd[vl * 8 + kg] = bestD;
    s_pi[vl * 8 + kg] = bestI;
    __syncthreads();

    // combine across kg ascending, publish chunk partials
    if (tid < VT) {
        float bd = INFINITY;
        int   bi = 0;
        for (int g = 0; g < 8; g++) {
            const float d2 = s_pd[tid * 8 + g];
            if (d2 < bd) { bd = d2; bi = s_pi[tid * 8 + g]; }
        }
        g_pd[(v0 + tid) * NCHUNK + chunk] = bd;
        g_pi[(v0 + tid) * NCHUNK + chunk] = bi;
    }

    // ---- per-vtile last block: combine chunks, fill LUTs ----
    __threadfence();
    if (tid == 0) {
        const int ticket = atomicAdd(&g_tile_cnt[vtile], 1);
        s_last = (ticket == NCHUNK - 1) ? 1 : 0;
    }
    __syncthreads();

    if (s_last) {
        __threadfence();
        if (tid < VT) {
            const int v = v0 + tid;
            float bd = INFINITY;
            int   bi = 0;
            for (int c = 0; c < NCHUNK; c++) {       // ascending chunk = ascending k
                const float d = g_pd[v * NCHUNK + c];
                if (d < bd) { bd = d; bi = g_pi[v * NCHUNK + c]; }
            }
            s_bestv[tid] = bi;
            g_idx_f[v]   = (float)bi;

            const float* e  = cb + (size_t)bi * DDIM;
            const float* zp = g_z + v * DDIM;
            double a0 = 0.0, a1 = 0.0, a2 = 0.0, a3 = 0.0;
            for (int d = 0; d < DDIM; d += 4) {
                const double f0 = (double)e[d + 0] - (double)zp[d + 0];
                const double f1 = (double)e[d + 1] - (double)zp[d + 1];
                const double f2 = (double)e[d + 2] - (double)zp[d + 2];
                const double f3 = (double)e[d + 3] - (double)zp[d + 3];
                a0 += f0 * f0; a1 += f1 * f1; a2 += f2 * f2; a3 += f3 * f3;
            }
            g_err_lut[v] = (a0 + a1) + (a2 + a3);
        }
        __syncthreads();

        float* q_lut = reinterpret_cast<float*>(g_q_lut4);
        for (int idx = tid; idx < VT * DDIM; idx += 256) {
            const int vvl = idx >> 6, d = idx & 63;
            q_lut[(v0 + vvl) * DDIM + d] = cb[(size_t)s_bestv[vvl] * DDIM + d];
        }
        if (tid == 0) g_tile_cnt[vtile] = 0;         // clean for next replay

        // ---- ticket-of-tickets: last vtile-last block computes the loss ----
        __threadfence();
        if (tid == 0) {
            const int gt = atomicAdd(&g_ticket, 1);
            s_glast = (gt == VTILES - 1) ? 1 : 0;
        }
        __syncthreads();
        if (s_glast) {
            __threadfence();
            if (tid == 0) g_ticket = 0;              // clean for next replay
            if (loss_out != nullptr) {
                dacc[tid] = (double)g_cnt[tid]       * g_err_lut[tid]
                          + (double)g_cnt[tid + 256] * g_err_lut[tid + 256];
                __syncthreads();
                for (int off = 128; off > 0; off >>= 1) {
                    if (tid < off) dacc[tid] += dacc[tid + off];
                    __syncthreads();
                }
                if (tid == 0)
                    loss_out[0] = (float)(1.25 * dacc[0] /
                                          ((double)n * (double)DDIM));
            }
        }
    }
}

// ---------------------------------------------------------------------------
// Kernel 2: scatter with SMEM-resident LUT. 148 blocks x 1024 threads,
// 130 KB dynamic smem (1 block/SM, exactly one wave). Each block stages the
// full 128 KB q-LUT + 2 KB idx table once, then every gather is an LDS
// instead of an L2 round-trip. Stores stay the proven coalesced pattern.
// Block 0 resets g_cnt for the next graph replay.
// ---------------------------------------------------------------------------
__global__ __launch_bounds__(SC_TPB, 1)
void scatter_kernel(const int* __restrict__ t,
                    float4* __restrict__ q_out,
                    float* __restrict__ idx_out, int n) {
    extern __shared__ float4 s_lut[];                  // [KCODES*16]
    float* s_idx = reinterpret_cast<float*>(s_lut + KCODES * 16);

    // stage LUT + idx (coalesced; L2-resident after dist_kernel)
    for (int j = threadIdx.x; j < KCODES * 16; j += SC_TPB)
        s_lut[j] = g_q_lut4[j];
    if (threadIdx.x < KCODES)
        s_idx[threadIdx.x] = g_idx_f[threadIdx.x];
    if (blockIdx.x == 0 && threadIdx.x < KCODES)       // reset hist for replay
        g_cnt[threadIdx.x] = 0;
    __syncthreads();

    const int total  = n * 16;
    const int stride = SC_GRID * SC_TPB;
    const int i0     = blockIdx.x * SC_TPB + threadIdx.x;

    for (int base = i0; base < total; base += stride * 4) {
        int    v[4];
        float4 val[4];
        #pragma unroll
        for (int j = 0; j < 4; j++) {
            const int i = base + j * stride;
            if (i < total) {
                v[j]   = __ldg(t + (i >> 4));
                val[j] = s_lut[(v[j] << 4) + (i & 15)];
            } else {
                v[j] = -1;
            }
        }
        #pragma unroll
        for (int j = 0; j < 4; j++) {
            const int i = base + j * stride;
            if (v[j] >= 0) {
                q_out[i] = val[j];
                if ((i & 15) == 0 && idx_out != nullptr)
                    idx_out[i >> 4] = s_idx[v[j]];
            }
        }
    }
}

// ---------------------------------------------------------------------------
extern "C" void kernel_launch(void* const* d_in, const int* in_sizes, int n_in,
                              void* d_out, int out_size) {
    const int*   t    = (const int*)d_in[0];
    const float* W1   = (const float*)d_in[1];
    const float* b1   = (const float*)d_in[2];
    const float* lng  = (const float*)d_in[3];
    const float* lnb  = (const float*)d_in[4];
    const float* W2   = (const float*)d_in[5];
    const float* b2   = (const float*)d_in[6];
    const float* cb   = (const float*)d_in[7];

    const int n = in_sizes[0];                 // N = B*T = 262144 tokens
    float* out = (float*)d_out;

    // Output layout: [ q : n*64 floats | idx : n floats | loss : 1 float ]
    const bool full = (out_size >= n * DDIM + n + 1);
    float* q_out    = out;
    float* idx_out  = full ? (out + (size_t)n * DDIM) : nullptr;
    float* loss_out = full ? (out + (size_t)n * DDIM + n) : nullptr;

    // allow 130 KB dynamic smem for the scatter (host-side attribute, not
    // stream-ordered -> graph-capture safe; idempotent)
    static bool attr_set = false;
    if (!attr_set) {
        cudaFuncSetAttribute(scatter_kernel,
                             cudaFuncAttributeMaxDynamicSharedMemorySize,
                             SC_SMEM);
        attr_set = true;
    }

    dist_kernel<<<NBLK, 256>>>(W1, b1, lng, lnb, W2, b2, cb, t, loss_out, n);
    scatter_kernel<<<SC_GRID, SC_TPB, SC_SMEM>>>(t, (float4*)q_out, idx_out, n);
}